// round 5
// baseline (speedup 1.0000x reference)
#include <cuda_runtime.h>
#include <math.h>

// Problem constants
#define BB   2
#define NN   2048
#define RRoi 128
#define CINv 256
#define NSv  16
#define C1v  128
#define RADv 0.3f
#define EPSv 1e-5f
#define FEATS_SZ (BB*C1v*NN)          // 524288
#define GRID_SZ  (BB*RRoi*125*C1v)    // 4096000

// ---------------- scratch ----------------
__device__ int   g_idx[BB*NN*NSv];
__device__ float g_Gt[BB*NN*256];        // [b][j][o]  (o contiguous)
__device__ float g_hmax[BB*256*NN];      // [b][o][n]
__device__ float g_h2[BB*C1v*NN];        // [b][o][n]
__device__ float g_h3[BB*C1v*NN];        // [b][o][n]
__device__ float g_featsT[BB*NN*C1v];    // [b][n][c]
__device__ float g_WfT[256*256];         // [c][o]
__device__ float g_WxT[3*256];           // [k][o]
__device__ float g_W1T[256*C1v];         // [c][o]
__device__ float g_W2T[C1v*C1v];         // [c][o]
__device__ int   g_roilst[BB*RRoi*NN];   // packed (vox<<12)|n per roi
__device__ int   g_roicnt[BB*RRoi];
// stats: [0:256) sum1 [256:512) sq1 [512:640) sum2 [640:768) sq2 [768:896) sum3 [896:1024) sq3
__device__ float g_stats[1024];

// ---------------- fused front: weight transposes + neighbor scan + roi classify ----------------
__global__ void k_front(const float* __restrict__ pts, const float* __restrict__ rois,
                        const float* __restrict__ Wm, const float* __restrict__ W1,
                        const float* __restrict__ W2) {
    __shared__ __align__(16) char sbuf[24576];
    int blk = blockIdx.x;
    if (blk < 452) {
        int id = blk * 256 + threadIdx.x;
        if (id < 65536) {                      // WfT[c][o] = Wm[o][3+c]
            int o = id & 255, c = id >> 8;
            g_WfT[id] = Wm[o * 259 + 3 + c];
        } else if (id < 66304) {               // WxT[k][o]
            int t = id - 65536; int o = t & 255, k = t >> 8;
            g_WxT[t] = Wm[o * 259 + k];
        } else if (id < 99072) {               // W1T[c][o]
            int t = id - 66304; int o = t & 127, c = t >> 7;
            g_W1T[t] = W1[o * 256 + c];
        } else if (id < 115456) {              // W2T[c][o]
            int t = id - 99072; int o = t & 127, c = t >> 7;
            g_W2T[t] = W2[o * 128 + c];
        }
    } else if (blk < 964) {
        // ---- neighbor search: warp-per-point ballot scan ----
        int q = blk - 452;
        int b = q >> 8, chunk = q & 255;
        float* sx = (float*)sbuf;
        float* sy = sx + NN;
        float* sz = sx + 2 * NN;
        const float* P = pts + (size_t)b * NN * 3;
        for (int j = threadIdx.x; j < NN; j += 256) {
            sx[j] = P[j * 3 + 0]; sy[j] = P[j * 3 + 1]; sz[j] = P[j * 3 + 2];
        }
        __syncthreads();
        int warp = threadIdx.x >> 5, lane = threadIdx.x & 31;
        int i = chunk * 8 + warp;
        float xi = sx[i], yi = sy[i], zi = sz[i];
        int base = (b * NN + i) * NSv;
        const float r2 = RADv * RADv;
        int cnt = 0, f0 = -1;
        for (int j0 = 0; j0 < NN; j0 += 32) {
            int j = j0 + lane;
            float dx = sx[j] - xi, dy = sy[j] - yi, dz = sz[j] - zi;
            bool qq = (dx * dx + dy * dy + dz * dz) < r2;
            unsigned m = __ballot_sync(0xffffffffu, qq);
            if (m) {
                if (f0 < 0) f0 = j0 + __ffs(m) - 1;
                int pos = cnt + __popc(m & ((1u << lane) - 1u));
                if (qq && pos < NSv) g_idx[base + pos] = j;
                cnt += __popc(m);
                if (cnt >= NSv) break;
            }
        }
        if (cnt < NSv) {
            for (int s = cnt + lane; s < NSv; s += 32) g_idx[base + s] = f0;
        }
    } else {
        // ---- roi point-in-box classify ----
        int br = blk - 964;
        int b = br >> 7;
        int* cnt = (int*)sbuf;
        if (threadIdx.x == 0) *cnt = 0;
        __syncthreads();
        const float* qr = rois + (size_t)br * 7;
        float cx = qr[0], cy = qr[1], cz = qr[2];
        float hx = qr[3] * 0.5f, hy = qr[4] * 0.5f, hz = qr[5] * 0.5f;
        float co = cosf(qr[6]), si = sinf(qr[6]);
        const float* P = pts + (size_t)b * NN * 3;
        int* lst = g_roilst + (size_t)br * NN;
        for (int n = threadIdx.x; n < NN; n += 256) {
            float rx = P[n * 3 + 0] - cx;
            float ry = P[n * 3 + 1] - cy;
            float rz = P[n * 3 + 2] - cz;
            float lx = rx * co + ry * si;
            float ly = -rx * si + ry * co;
            float lz = rz;
            if (fabsf(lx) < hx && fabsf(ly) < hy && fabsf(lz) < hz) {
                int v0 = (int)fminf(fmaxf(floorf((lx + hx) / (2.f * hx) * 5.f), 0.f), 4.f);
                int v1 = (int)fminf(fmaxf(floorf((ly + hy) / (2.f * hy) * 5.f), 0.f), 4.f);
                int v2 = (int)fminf(fmaxf(floorf((lz + hz) / (2.f * hz) * 5.f), 0.f), 4.f);
                int vox = (v0 * 5 + v1) * 5 + v2;
                int pos = atomicAdd(cnt, 1);
                lst[pos] = (vox << 12) | n;
            }
        }
        __syncthreads();
        if (threadIdx.x == 0) g_roicnt[br] = *cnt;
    }
}

// ---------------- GEMM G: Gt[b][j][o] = sum_c feat[b][c][j] * WfT[c][o]
// 32(j) x 64(o) tiles, 256 threads, 2x4 acc, double-buffered. grid=512.
__global__ void k_gemmG(const float* __restrict__ feat) {
    __shared__ float As[2][16][32];  // [k][j]
    __shared__ float Bs[2][16][64];  // [k][o]
    int b = blockIdx.z;
    int j0 = blockIdx.x * 32, o0 = blockIdx.y * 64;
    int tid = threadIdx.x;
    int tx = tid & 15, ty = tid >> 4;        // tx -> o*4, ty -> j*2
    int alk = tid >> 3, alc = (tid & 7) * 4; // tid<128 loads As
    int blk_ = tid >> 4, blc = (tid & 15) * 4;
    const float* Asrc = feat + (size_t)(b * CINv) * NN;
    if (tid < 128)
        *(float4*)&As[0][alk][alc] = *(const float4*)&Asrc[(size_t)alk * NN + j0 + alc];
    *(float4*)&Bs[0][blk_][blc] = *(const float4*)&g_WfT[blk_ * 256 + o0 + blc];
    __syncthreads();
    float acc[2][4] = {};
    int buf = 0;
    for (int t = 0; t < 16; t++) {
        float4 a_reg, b_reg;
        if (t < 15) {
            int k0 = (t + 1) * 16;
            if (tid < 128)
                a_reg = *(const float4*)&Asrc[(size_t)(k0 + alk) * NN + j0 + alc];
            b_reg = *(const float4*)&g_WfT[(k0 + blk_) * 256 + o0 + blc];
        }
        #pragma unroll
        for (int kk = 0; kk < 16; kk++) {
            float2 a2 = *(const float2*)&As[buf][kk][ty * 2];
            float4 b4 = *(const float4*)&Bs[buf][kk][tx * 4];
            acc[0][0] += a2.x * b4.x; acc[0][1] += a2.x * b4.y;
            acc[0][2] += a2.x * b4.z; acc[0][3] += a2.x * b4.w;
            acc[1][0] += a2.y * b4.x; acc[1][1] += a2.y * b4.y;
            acc[1][2] += a2.y * b4.z; acc[1][3] += a2.y * b4.w;
        }
        if (t < 15) {
            if (tid < 128) *(float4*)&As[buf ^ 1][alk][alc] = a_reg;
            *(float4*)&Bs[buf ^ 1][blk_][blc] = b_reg;
        }
        __syncthreads();
        buf ^= 1;
    }
    #pragma unroll
    for (int i = 0; i < 2; i++) {
        float4 st = make_float4(acc[i][0], acc[i][1], acc[i][2], acc[i][3]);
        *(float4*)&g_Gt[(size_t)(b * NN + j0 + ty * 2 + i) * 256 + o0 + tx * 4] = st;
    }
}

// ---------------- gather + xyz MLP + max over samples + BN1 stats (float4 gather) ----------------
#define PPB 8
__global__ void k_gathermax(const float* __restrict__ pts) {
    __shared__ int   sj[PPB * NSv];
    __shared__ float srx[PPB * NSv], sry[PPB * NSv], srz[PPB * NSv];
    __shared__ float stile[256 * (PPB + 1)];
    __shared__ float ssum[4][256], ssq[4][256];
    int b = blockIdx.y;
    int n0 = blockIdx.x * PPB;
    int tid = threadIdx.x;
    if (tid < PPB * NSv) {
        int p = tid >> 4, s = tid & 15;
        int n = n0 + p;
        int j = g_idx[(b * NN + n) * NSv + s];
        sj[tid] = j;
        const float* P = pts + (size_t)b * NN * 3;
        srx[tid] = (P[j * 3 + 0] - P[n * 3 + 0]) / RADv;
        sry[tid] = (P[j * 3 + 1] - P[n * 3 + 1]) / RADv;
        srz[tid] = (P[j * 3 + 2] - P[n * 3 + 2]) / RADv;
    }
    __syncthreads();
    int co = tid & 63;
    int pg = tid >> 6;
    float4 w0 = *(const float4*)&g_WxT[co * 4];
    float4 w1 = *(const float4*)&g_WxT[256 + co * 4];
    float4 w2 = *(const float4*)&g_WxT[512 + co * 4];
    float4 ls = make_float4(0.f, 0.f, 0.f, 0.f);
    float4 lq = make_float4(0.f, 0.f, 0.f, 0.f);
    const float* Gb = g_Gt + (size_t)b * NN * 256;
    #pragma unroll
    for (int pp = 0; pp < 2; pp++) {
        int p = pg * 2 + pp;
        float4 m = make_float4(-3.4e38f, -3.4e38f, -3.4e38f, -3.4e38f);
        #pragma unroll
        for (int s = 0; s < NSv; s++) {
            int e = p * NSv + s;
            int j = sj[e];
            float rx = srx[e], ry = sry[e], rz = srz[e];
            float4 gv = *(const float4*)&Gb[(size_t)j * 256 + co * 4];
            float4 v;
            v.x = gv.x + w0.x * rx + w1.x * ry + w2.x * rz;
            v.y = gv.y + w0.y * rx + w1.y * ry + w2.y * rz;
            v.z = gv.z + w0.z * rx + w1.z * ry + w2.z * rz;
            v.w = gv.w + w0.w * rx + w1.w * ry + w2.w * rz;
            m.x = fmaxf(m.x, v.x); m.y = fmaxf(m.y, v.y);
            m.z = fmaxf(m.z, v.z); m.w = fmaxf(m.w, v.w);
            ls.x += v.x; ls.y += v.y; ls.z += v.z; ls.w += v.w;
            lq.x += v.x * v.x; lq.y += v.y * v.y; lq.z += v.z * v.z; lq.w += v.w * v.w;
        }
        stile[(co * 4 + 0) * (PPB + 1) + p] = m.x;
        stile[(co * 4 + 1) * (PPB + 1) + p] = m.y;
        stile[(co * 4 + 2) * (PPB + 1) + p] = m.z;
        stile[(co * 4 + 3) * (PPB + 1) + p] = m.w;
    }
    ssum[pg][co * 4 + 0] = ls.x; ssum[pg][co * 4 + 1] = ls.y;
    ssum[pg][co * 4 + 2] = ls.z; ssum[pg][co * 4 + 3] = ls.w;
    ssq[pg][co * 4 + 0] = lq.x; ssq[pg][co * 4 + 1] = lq.y;
    ssq[pg][co * 4 + 2] = lq.z; ssq[pg][co * 4 + 3] = lq.w;
    __syncthreads();
    #pragma unroll
    for (int r = 0; r < 256; r += 32) {
        int row = r + (tid >> 3);
        int col = tid & 7;
        g_hmax[(size_t)(b * 256 + row) * NN + n0 + col] = stile[row * (PPB + 1) + col];
    }
    float ts = ssum[0][tid] + ssum[1][tid] + ssum[2][tid] + ssum[3][tid];
    float tq = ssq[0][tid] + ssq[1][tid] + ssq[2][tid] + ssq[3][tid];
    atomicAdd(&g_stats[tid], ts);
    atomicAdd(&g_stats[256 + tid], tq);
}

// ---------------- GEMM1: h2 = b1 + W1 @ relu(bn1(hmax)), fused BN2 stats
// 64(n) x 32(o) tiles, 256 threads, 2x4 acc, double-buffered. grid=256.
__global__ void k_gemm1(const float* __restrict__ gm, const float* __restrict__ btm,
                        const float* __restrict__ b1) {
    __shared__ float As[2][16][64];  // [k][n]
    __shared__ float Bs[2][16][32];  // [k][o]
    __shared__ float ssc[256], ssh[256];
    int b = blockIdx.z;
    int n0 = blockIdx.x * 64, o0 = blockIdx.y * 32;
    int tid = threadIdx.x;
    int tx = tid & 15, ty = tid >> 4;        // tx -> n*4, ty -> o*2
    int alk = tid >> 4, alc = (tid & 15) * 4;  // all 256 load As
    int blk_ = tid >> 3, blc = (tid & 7) * 4;  // tid<128 load Bs
    {
        float m = g_stats[tid] * (1.f / 65536.f);
        float v = g_stats[256 + tid] * (1.f / 65536.f) - m * m;
        float sc = gm[tid] * rsqrtf(v + EPSv);
        ssc[tid] = sc; ssh[tid] = btm[tid] - m * sc;
    }
    __syncthreads();
    const float* Asrc = g_hmax + (size_t)(b * 256) * NN;
    {
        float4 a = *(const float4*)&Asrc[(size_t)alk * NN + n0 + alc];
        float sc = ssc[alk], sh = ssh[alk];
        a.x = fmaxf(a.x * sc + sh, 0.f); a.y = fmaxf(a.y * sc + sh, 0.f);
        a.z = fmaxf(a.z * sc + sh, 0.f); a.w = fmaxf(a.w * sc + sh, 0.f);
        *(float4*)&As[0][alk][alc] = a;
        if (tid < 128)
            *(float4*)&Bs[0][blk_][blc] = *(const float4*)&g_W1T[blk_ * C1v + o0 + blc];
    }
    __syncthreads();
    float acc[2][4] = {};
    int buf = 0;
    for (int t = 0; t < 16; t++) {
        float4 a_reg, b_reg;
        if (t < 15) {
            int k0 = (t + 1) * 16;
            a_reg = *(const float4*)&Asrc[(size_t)(k0 + alk) * NN + n0 + alc];
            if (tid < 128)
                b_reg = *(const float4*)&g_W1T[(k0 + blk_) * C1v + o0 + blc];
        }
        #pragma unroll
        for (int kk = 0; kk < 16; kk++) {
            float4 a4 = *(const float4*)&As[buf][kk][tx * 4];
            float2 b2 = *(const float2*)&Bs[buf][kk][ty * 2];
            acc[0][0] += b2.x * a4.x; acc[0][1] += b2.x * a4.y;
            acc[0][2] += b2.x * a4.z; acc[0][3] += b2.x * a4.w;
            acc[1][0] += b2.y * a4.x; acc[1][1] += b2.y * a4.y;
            acc[1][2] += b2.y * a4.z; acc[1][3] += b2.y * a4.w;
        }
        if (t < 15) {
            int k0 = (t + 1) * 16;
            float sc = ssc[k0 + alk], sh = ssh[k0 + alk];
            a_reg.x = fmaxf(a_reg.x * sc + sh, 0.f); a_reg.y = fmaxf(a_reg.y * sc + sh, 0.f);
            a_reg.z = fmaxf(a_reg.z * sc + sh, 0.f); a_reg.w = fmaxf(a_reg.w * sc + sh, 0.f);
            *(float4*)&As[buf ^ 1][alk][alc] = a_reg;
            if (tid < 128) *(float4*)&Bs[buf ^ 1][blk_][blc] = b_reg;
        }
        __syncthreads();
        buf ^= 1;
    }
    float psum[2], psq[2];
    #pragma unroll
    for (int i = 0; i < 2; i++) {
        int oy = o0 + ty * 2 + i;
        float bias = b1[oy];
        float s = 0.f, q = 0.f;
        #pragma unroll
        for (int jn = 0; jn < 4; jn++) {
            float h = acc[i][jn] + bias;
            acc[i][jn] = h; s += h; q += h * h;
        }
        psum[i] = s; psq[i] = q;
        float4 st = make_float4(acc[i][0], acc[i][1], acc[i][2], acc[i][3]);
        *(float4*)&g_h2[(size_t)(b * C1v + oy) * NN + n0 + tx * 4] = st;
    }
    // reduce over the 16 tx lanes (half-warp groups share ty)
    #pragma unroll
    for (int i = 0; i < 2; i++) {
        #pragma unroll
        for (int off = 8; off > 0; off >>= 1) {
            psum[i] += __shfl_down_sync(0xffffffffu, psum[i], off, 16);
            psq[i]  += __shfl_down_sync(0xffffffffu, psq[i],  off, 16);
        }
    }
    if (tx == 0) {
        #pragma unroll
        for (int i = 0; i < 2; i++) {
            int oy = o0 + ty * 2 + i;
            atomicAdd(&g_stats[512 + oy], psum[i]);
            atomicAdd(&g_stats[640 + oy], psq[i]);
        }
    }
}

// ---------------- GEMM2: h3 = b2 + W2 @ relu(bn2(h2)), fused BN3 stats
// 64(n) x 32(o) tiles, 256 threads, 2x4 acc, double-buffered. grid=256.
__global__ void k_gemm2(const float* __restrict__ g1, const float* __restrict__ bt1,
                        const float* __restrict__ b2) {
    __shared__ float As[2][16][64];
    __shared__ float Bs[2][16][32];
    __shared__ float ssc[128], ssh[128];
    int b = blockIdx.z;
    int n0 = blockIdx.x * 64, o0 = blockIdx.y * 32;
    int tid = threadIdx.x;
    int tx = tid & 15, ty = tid >> 4;
    int alk = tid >> 4, alc = (tid & 15) * 4;
    int blk_ = tid >> 3, blc = (tid & 7) * 4;
    if (tid < 128) {
        float m = g_stats[512 + tid] * (1.f / 4096.f);
        float v = g_stats[640 + tid] * (1.f / 4096.f) - m * m;
        float sc = g1[tid] * rsqrtf(v + EPSv);
        ssc[tid] = sc; ssh[tid] = bt1[tid] - m * sc;
    }
    __syncthreads();
    const float* Asrc = g_h2 + (size_t)(b * C1v) * NN;
    {
        float4 a = *(const float4*)&Asrc[(size_t)alk * NN + n0 + alc];
        float sc = ssc[alk], sh = ssh[alk];
        a.x = fmaxf(a.x * sc + sh, 0.f); a.y = fmaxf(a.y * sc + sh, 0.f);
        a.z = fmaxf(a.z * sc + sh, 0.f); a.w = fmaxf(a.w * sc + sh, 0.f);
        *(float4*)&As[0][alk][alc] = a;
        if (tid < 128)
            *(float4*)&Bs[0][blk_][blc] = *(const float4*)&g_W2T[blk_ * C1v + o0 + blc];
    }
    __syncthreads();
    float acc[2][4] = {};
    int buf = 0;
    for (int t = 0; t < 8; t++) {
        float4 a_reg, b_reg;
        if (t < 7) {
            int k0 = (t + 1) * 16;
            a_reg = *(const float4*)&Asrc[(size_t)(k0 + alk) * NN + n0 + alc];
            if (tid < 128)
                b_reg = *(const float4*)&g_W2T[(k0 + blk_) * C1v + o0 + blc];
        }
        #pragma unroll
        for (int kk = 0; kk < 16; kk++) {
            float4 a4 = *(const float4*)&As[buf][kk][tx * 4];
            float2 b2 = *(const float2*)&Bs[buf][kk][ty * 2];
            acc[0][0] += b2.x * a4.x; acc[0][1] += b2.x * a4.y;
            acc[0][2] += b2.x * a4.z; acc[0][3] += b2.x * a4.w;
            acc[1][0] += b2.y * a4.x; acc[1][1] += b2.y * a4.y;
            acc[1][2] += b2.y * a4.z; acc[1][3] += b2.y * a4.w;
        }
        if (t < 7) {
            int k0 = (t + 1) * 16;
            float sc = ssc[k0 + alk], sh = ssh[k0 + alk];
            a_reg.x = fmaxf(a_reg.x * sc + sh, 0.f); a_reg.y = fmaxf(a_reg.y * sc + sh, 0.f);
            a_reg.z = fmaxf(a_reg.z * sc + sh, 0.f); a_reg.w = fmaxf(a_reg.w * sc + sh, 0.f);
            *(float4*)&As[buf ^ 1][alk][alc] = a_reg;
            if (tid < 128) *(float4*)&Bs[buf ^ 1][blk_][blc] = b_reg;
        }
        __syncthreads();
        buf ^= 1;
    }
    float psum[2], psq[2];
    #pragma unroll
    for (int i = 0; i < 2; i++) {
        int oy = o0 + ty * 2 + i;
        float bias = b2[oy];
        float s = 0.f, q = 0.f;
        #pragma unroll
        for (int jn = 0; jn < 4; jn++) {
            float h = acc[i][jn] + bias;
            acc[i][jn] = h; s += h; q += h * h;
        }
        psum[i] = s; psq[i] = q;
        float4 st = make_float4(acc[i][0], acc[i][1], acc[i][2], acc[i][3]);
        *(float4*)&g_h3[(size_t)(b * C1v + oy) * NN + n0 + tx * 4] = st;
    }
    #pragma unroll
    for (int i = 0; i < 2; i++) {
        #pragma unroll
        for (int off = 8; off > 0; off >>= 1) {
            psum[i] += __shfl_down_sync(0xffffffffu, psum[i], off, 16);
            psq[i]  += __shfl_down_sync(0xffffffffu, psq[i],  off, 16);
        }
    }
    if (tx == 0) {
        #pragma unroll
        for (int i = 0; i < 2; i++) {
            int oy = o0 + ty * 2 + i;
            atomicAdd(&g_stats[768 + oy], psum[i]);
            atomicAdd(&g_stats[896 + oy], psq[i]);
        }
    }
}

// ---------------- final feats: BN3+ReLU, tiled transpose (both writes coalesced) ----------------
__global__ void k_feats(const float* __restrict__ g2, const float* __restrict__ bt2,
                        float* __restrict__ out) {
    __shared__ float t[32][33];
    __shared__ float ssc[32], ssh[32];
    int b = blockIdx.z;
    int n0 = blockIdx.x * 32, o0 = blockIdx.y * 32;
    int tid = threadIdx.x;
    int tx = tid & 31, ty = tid >> 5;          // 32x8
    if (tid < 32) {
        int o = o0 + tid;
        float m = g_stats[768 + o] * (1.f / 4096.f);
        float v = g_stats[896 + o] * (1.f / 4096.f) - m * m;
        float sc = g2[o] * rsqrtf(v + EPSv);
        ssc[tid] = sc; ssh[tid] = bt2[o] - m * sc;
    }
    __syncthreads();
    #pragma unroll
    for (int r = 0; r < 4; r++) {
        int oo = ty + r * 8;
        int o = o0 + oo;
        size_t e = (size_t)(b * C1v + o) * NN + n0 + tx;
        float f = fmaxf(g_h3[e] * ssc[oo] + ssh[oo], 0.f);
        out[e] = f;
        t[oo][tx] = f;
    }
    __syncthreads();
    #pragma unroll
    for (int r = 0; r < 4; r++) {
        int nn = ty + r * 8;
        g_featsT[(size_t)(b * NN + n0 + nn) * C1v + o0 + tx] = t[tx][nn];
    }
}

// ---------------- RoI voxel max-pool: smem grid, parallel over points via smem atomicMax ----------------
__global__ void k_roipool(float* __restrict__ out) {
    extern __shared__ float sg[];            // 125*128 floats
    int br = blockIdx.x;
    int b = br >> 7;
    int t = threadIdx.x;                     // 512
    for (int i = t; i < 125 * C1v / 4; i += 512)
        ((float4*)sg)[i] = make_float4(0.f, 0.f, 0.f, 0.f);
    __syncthreads();
    const float* F = g_featsT + (size_t)b * NN * C1v;
    const int* lst = g_roilst + (size_t)br * NN;
    int m = g_roicnt[br];
    int ch = t & 127;
    int slot = t >> 7;                       // 0..3
    for (int e = slot; e < m; e += 4) {
        int pk = lst[e];
        int n = pk & 4095;
        int vox = pk >> 12;
        float val = F[(size_t)n * C1v + ch];
        atomicMax((int*)&sg[vox * C1v + ch], __float_as_int(val));
    }
    __syncthreads();
    float4* og = (float4*)(out + FEATS_SZ + (size_t)br * 125 * C1v);
    for (int i = t; i < 125 * C1v / 4; i += 512) og[i] = ((float4*)sg)[i];
}

// ---------------- launch ----------------
extern "C" void kernel_launch(void* const* d_in, const int* in_sizes, int n_in,
                              void* d_out, int out_size) {
    const float* pts    = (const float*)d_in[0];
    const float* feat   = (const float*)d_in[1];
    const float* rois   = (const float*)d_in[2];
    const float* W_mlp  = (const float*)d_in[3];
    const float* g_mlp  = (const float*)d_in[4];
    const float* btm    = (const float*)d_in[5];
    const float* W1     = (const float*)d_in[6];
    const float* b1     = (const float*)d_in[7];
    const float* g1     = (const float*)d_in[8];
    const float* bt1    = (const float*)d_in[9];
    const float* W2     = (const float*)d_in[10];
    const float* b2     = (const float*)d_in[11];
    const float* g2     = (const float*)d_in[12];
    const float* bt2    = (const float*)d_in[13];
    float* out = (float*)d_out;

    cudaFuncSetAttribute(k_roipool, cudaFuncAttributeMaxDynamicSharedMemorySize,
                         125 * C1v * sizeof(float));

    void* statsPtr = nullptr;
    cudaGetSymbolAddress(&statsPtr, g_stats);
    cudaMemsetAsync(statsPtr, 0, 1024 * sizeof(float), 0);

    k_front<<<1220, 256>>>(pts, rois, W_mlp, W1, W2);
    k_gemmG<<<dim3(NN / 32, 256 / 64, BB), 256>>>(feat);
    k_gathermax<<<dim3(NN / PPB, BB), 256>>>(pts);
    k_gemm1<<<dim3(NN / 64, C1v / 32, BB), 256>>>(g_mlp, btm, b1);
    k_gemm2<<<dim3(NN / 64, C1v / 32, BB), 256>>>(g1, bt1, b2);
    k_feats<<<dim3(NN / 32, C1v / 32, BB), 256>>>(g2, bt2, out);
    k_roipool<<<BB * RRoi, 512, 125 * C1v * sizeof(float)>>>(out);
}

// round 6
// speedup vs baseline: 1.1190x; 1.1190x over previous
#include <cuda_runtime.h>
#include <math.h>

// Problem constants
#define BB   2
#define NN   2048
#define RRoi 128
#define CINv 256
#define NSv  16
#define C1v  128
#define RADv 0.3f
#define EPSv 1e-5f
#define FEATS_SZ (BB*C1v*NN)          // 524288
#define GRID_SZ  (BB*RRoi*125*C1v)    // 4096000

// ---------------- scratch ----------------
__device__ int   g_idx[BB*NN*NSv];
__device__ float g_Gt[BB*NN*256];        // [b][j][o]  (o contiguous)
__device__ float g_hmax[BB*256*NN];      // [b][o][n]
__device__ float g_h2[BB*C1v*NN];        // [b][o][n]
__device__ float g_h3[BB*C1v*NN];        // [b][o][n]
__device__ float g_featsT[BB*NN*C1v];    // [b][n][c]
__device__ float g_WfT[256*256];         // [c][o]
__device__ float g_WxT[3*256];           // [k][o]
__device__ float g_W1T[256*C1v];         // [c][o]
__device__ float g_W2T[C1v*C1v];         // [c][o]
__device__ int   g_roilst[BB*RRoi*NN];   // packed (vox<<12)|n per roi
__device__ int   g_roicnt[BB*RRoi];
// stats: [0:256) sum1 [256:512) sq1 [512:640) sum2 [640:768) sq2 [768:896) sum3 [896:1024) sq3
__device__ float g_stats[1024];

// ---------------- fused front: weight transposes + neighbor scan + roi classify ----------------
__global__ void k_front(const float* __restrict__ pts, const float* __restrict__ rois,
                        const float* __restrict__ Wm, const float* __restrict__ W1,
                        const float* __restrict__ W2) {
    __shared__ __align__(16) char sbuf[24576];
    int blk = blockIdx.x;
    if (blk < 452) {
        int id = blk * 256 + threadIdx.x;
        if (id < 65536) {                      // WfT[c][o] = Wm[o][3+c]
            int o = id & 255, c = id >> 8;
            g_WfT[id] = Wm[o * 259 + 3 + c];
        } else if (id < 66304) {               // WxT[k][o]
            int t = id - 65536; int o = t & 255, k = t >> 8;
            g_WxT[t] = Wm[o * 259 + k];
        } else if (id < 99072) {               // W1T[c][o]
            int t = id - 66304; int o = t & 127, c = t >> 7;
            g_W1T[t] = W1[o * 256 + c];
        } else if (id < 115456) {              // W2T[c][o]
            int t = id - 99072; int o = t & 127, c = t >> 7;
            g_W2T[t] = W2[o * 128 + c];
        }
    } else if (blk < 964) {
        // ---- neighbor search: warp-per-point ballot scan ----
        int q = blk - 452;
        int b = q >> 8, chunk = q & 255;
        float* sx = (float*)sbuf;
        float* sy = sx + NN;
        float* sz = sx + 2 * NN;
        const float* P = pts + (size_t)b * NN * 3;
        for (int j = threadIdx.x; j < NN; j += 256) {
            sx[j] = P[j * 3 + 0]; sy[j] = P[j * 3 + 1]; sz[j] = P[j * 3 + 2];
        }
        __syncthreads();
        int warp = threadIdx.x >> 5, lane = threadIdx.x & 31;
        int i = chunk * 8 + warp;
        float xi = sx[i], yi = sy[i], zi = sz[i];
        int base = (b * NN + i) * NSv;
        const float r2 = RADv * RADv;
        int cnt = 0, f0 = -1;
        for (int j0 = 0; j0 < NN; j0 += 32) {
            int j = j0 + lane;
            float dx = sx[j] - xi, dy = sy[j] - yi, dz = sz[j] - zi;
            bool qq = (dx * dx + dy * dy + dz * dz) < r2;
            unsigned m = __ballot_sync(0xffffffffu, qq);
            if (m) {
                if (f0 < 0) f0 = j0 + __ffs(m) - 1;
                int pos = cnt + __popc(m & ((1u << lane) - 1u));
                if (qq && pos < NSv) g_idx[base + pos] = j;
                cnt += __popc(m);
                if (cnt >= NSv) break;
            }
        }
        if (cnt < NSv) {
            for (int s = cnt + lane; s < NSv; s += 32) g_idx[base + s] = f0;
        }
    } else {
        // ---- roi point-in-box classify ----
        int br = blk - 964;
        int b = br >> 7;
        int* cnt = (int*)sbuf;
        if (threadIdx.x == 0) *cnt = 0;
        __syncthreads();
        const float* qr = rois + (size_t)br * 7;
        float cx = qr[0], cy = qr[1], cz = qr[2];
        float hx = qr[3] * 0.5f, hy = qr[4] * 0.5f, hz = qr[5] * 0.5f;
        float co = cosf(qr[6]), si = sinf(qr[6]);
        const float* P = pts + (size_t)b * NN * 3;
        int* lst = g_roilst + (size_t)br * NN;
        for (int n = threadIdx.x; n < NN; n += 256) {
            float rx = P[n * 3 + 0] - cx;
            float ry = P[n * 3 + 1] - cy;
            float rz = P[n * 3 + 2] - cz;
            float lx = rx * co + ry * si;
            float ly = -rx * si + ry * co;
            float lz = rz;
            if (fabsf(lx) < hx && fabsf(ly) < hy && fabsf(lz) < hz) {
                int v0 = (int)fminf(fmaxf(floorf((lx + hx) / (2.f * hx) * 5.f), 0.f), 4.f);
                int v1 = (int)fminf(fmaxf(floorf((ly + hy) / (2.f * hy) * 5.f), 0.f), 4.f);
                int v2 = (int)fminf(fmaxf(floorf((lz + hz) / (2.f * hz) * 5.f), 0.f), 4.f);
                int vox = (v0 * 5 + v1) * 5 + v2;
                int pos = atomicAdd(cnt, 1);
                lst[pos] = (vox << 12) | n;
            }
        }
        __syncthreads();
        if (threadIdx.x == 0) g_roicnt[br] = *cnt;
    }
}

// ---------------- GEMM G: Gt[b][j][o] = sum_c feat[b][c][j] * WfT[c][o]
// (Round-4 proven shape: 64x64 tiles, 256 threads, 4x4 acc, double-buffered, grid=256)
__global__ void k_gemmG(const float* __restrict__ feat) {
    __shared__ float As[2][16][64];  // [kk][j]
    __shared__ float Bs[2][16][64];  // [kk][o]
    int b = blockIdx.z;
    int j0 = blockIdx.x * 64, o0 = blockIdx.y * 64;
    int tid = threadIdx.x;
    int tx = tid & 15, ty = tid >> 4;
    int lk = tid >> 4, lc = (tid & 15) * 4;
    const float* Asrc = feat + (size_t)(b * CINv) * NN;
    *(float4*)&As[0][lk][lc] = *(const float4*)&Asrc[(size_t)lk * NN + j0 + lc];
    *(float4*)&Bs[0][lk][lc] = *(const float4*)&g_WfT[lk * 256 + o0 + lc];
    __syncthreads();
    float acc[4][4] = {};
    int buf = 0;
    for (int t = 0; t < 16; t++) {
        float4 a_reg, b_reg;
        if (t < 15) {
            int k0 = (t + 1) * 16;
            a_reg = *(const float4*)&Asrc[(size_t)(k0 + lk) * NN + j0 + lc];
            b_reg = *(const float4*)&g_WfT[(k0 + lk) * 256 + o0 + lc];
        }
        #pragma unroll
        for (int kk = 0; kk < 16; kk++) {
            float4 a4 = *(const float4*)&As[buf][kk][ty * 4];
            float4 b4 = *(const float4*)&Bs[buf][kk][tx * 4];
            float av[4] = {a4.x, a4.y, a4.z, a4.w};
            float bv[4] = {b4.x, b4.y, b4.z, b4.w};
            #pragma unroll
            for (int i = 0; i < 4; i++)
                #pragma unroll
                for (int q = 0; q < 4; q++) acc[i][q] += av[i] * bv[q];
        }
        if (t < 15) {
            *(float4*)&As[buf ^ 1][lk][lc] = a_reg;
            *(float4*)&Bs[buf ^ 1][lk][lc] = b_reg;
        }
        __syncthreads();
        buf ^= 1;
    }
    #pragma unroll
    for (int i = 0; i < 4; i++) {
        float4 st = make_float4(acc[i][0], acc[i][1], acc[i][2], acc[i][3]);
        *(float4*)&g_Gt[(size_t)(b * NN + j0 + ty * 4 + i) * 256 + o0 + tx * 4] = st;
    }
}

// ---------------- gather + xyz MLP + max over samples + BN1 stats (float4 gather) ----------------
#define PPB 8
__global__ void k_gathermax(const float* __restrict__ pts) {
    __shared__ int   sj[PPB * NSv];
    __shared__ float srx[PPB * NSv], sry[PPB * NSv], srz[PPB * NSv];
    __shared__ float stile[256 * (PPB + 1)];
    __shared__ float ssum[4][256], ssq[4][256];
    int b = blockIdx.y;
    int n0 = blockIdx.x * PPB;
    int tid = threadIdx.x;
    if (tid < PPB * NSv) {
        int p = tid >> 4, s = tid & 15;
        int n = n0 + p;
        int j = g_idx[(b * NN + n) * NSv + s];
        sj[tid] = j;
        const float* P = pts + (size_t)b * NN * 3;
        srx[tid] = (P[j * 3 + 0] - P[n * 3 + 0]) / RADv;
        sry[tid] = (P[j * 3 + 1] - P[n * 3 + 1]) / RADv;
        srz[tid] = (P[j * 3 + 2] - P[n * 3 + 2]) / RADv;
    }
    __syncthreads();
    int co = tid & 63;
    int pg = tid >> 6;
    float4 w0 = *(const float4*)&g_WxT[co * 4];
    float4 w1 = *(const float4*)&g_WxT[256 + co * 4];
    float4 w2 = *(const float4*)&g_WxT[512 + co * 4];
    float4 ls = make_float4(0.f, 0.f, 0.f, 0.f);
    float4 lq = make_float4(0.f, 0.f, 0.f, 0.f);
    const float* Gb = g_Gt + (size_t)b * NN * 256;
    #pragma unroll
    for (int pp = 0; pp < 2; pp++) {
        int p = pg * 2 + pp;
        float4 m = make_float4(-3.4e38f, -3.4e38f, -3.4e38f, -3.4e38f);
        #pragma unroll
        for (int s = 0; s < NSv; s++) {
            int e = p * NSv + s;
            int j = sj[e];
            float rx = srx[e], ry = sry[e], rz = srz[e];
            float4 gv = *(const float4*)&Gb[(size_t)j * 256 + co * 4];
            float4 v;
            v.x = gv.x + w0.x * rx + w1.x * ry + w2.x * rz;
            v.y = gv.y + w0.y * rx + w1.y * ry + w2.y * rz;
            v.z = gv.z + w0.z * rx + w1.z * ry + w2.z * rz;
            v.w = gv.w + w0.w * rx + w1.w * ry + w2.w * rz;
            m.x = fmaxf(m.x, v.x); m.y = fmaxf(m.y, v.y);
            m.z = fmaxf(m.z, v.z); m.w = fmaxf(m.w, v.w);
            ls.x += v.x; ls.y += v.y; ls.z += v.z; ls.w += v.w;
            lq.x += v.x * v.x; lq.y += v.y * v.y; lq.z += v.z * v.z; lq.w += v.w * v.w;
        }
        stile[(co * 4 + 0) * (PPB + 1) + p] = m.x;
        stile[(co * 4 + 1) * (PPB + 1) + p] = m.y;
        stile[(co * 4 + 2) * (PPB + 1) + p] = m.z;
        stile[(co * 4 + 3) * (PPB + 1) + p] = m.w;
    }
    ssum[pg][co * 4 + 0] = ls.x; ssum[pg][co * 4 + 1] = ls.y;
    ssum[pg][co * 4 + 2] = ls.z; ssum[pg][co * 4 + 3] = ls.w;
    ssq[pg][co * 4 + 0] = lq.x; ssq[pg][co * 4 + 1] = lq.y;
    ssq[pg][co * 4 + 2] = lq.z; ssq[pg][co * 4 + 3] = lq.w;
    __syncthreads();
    #pragma unroll
    for (int r = 0; r < 256; r += 32) {
        int row = r + (tid >> 3);
        int col = tid & 7;
        g_hmax[(size_t)(b * 256 + row) * NN + n0 + col] = stile[row * (PPB + 1) + col];
    }
    float ts = ssum[0][tid] + ssum[1][tid] + ssum[2][tid] + ssum[3][tid];
    float tq = ssq[0][tid] + ssq[1][tid] + ssq[2][tid] + ssq[3][tid];
    atomicAdd(&g_stats[tid], ts);
    atomicAdd(&g_stats[256 + tid], tq);
}

// ---------------- GEMM1: h2 = b1 + W1 @ relu(bn1(hmax)), fused BN2 stats
// 64(n) x 32(o) tiles, 128 threads, 4x4 acc, double-buffered. grid=256.
__global__ void k_gemm1(const float* __restrict__ gm, const float* __restrict__ btm,
                        const float* __restrict__ b1) {
    __shared__ float As[2][16][64];  // [k][n]
    __shared__ float Bs[2][16][32];  // [k][o]
    __shared__ float ssc[256], ssh[256];
    int b = blockIdx.z;
    int n0 = blockIdx.x * 64, o0 = blockIdx.y * 32;
    int tid = threadIdx.x;               // 128
    int tx = tid & 15, ty = tid >> 4;    // tx -> n*4 (16), ty -> o*4 (8)
    int ar = tid >> 4, ac = (tid & 15) * 4;   // As rows ar, ar+8
    int br_ = tid >> 3, bc = (tid & 7) * 4;   // Bs row 0..15
    #pragma unroll
    for (int q = 0; q < 2; q++) {
        int c = tid + q * 128;
        float m = g_stats[c] * (1.f / 65536.f);
        float v = g_stats[256 + c] * (1.f / 65536.f) - m * m;
        float sc = gm[c] * rsqrtf(v + EPSv);
        ssc[c] = sc; ssh[c] = btm[c] - m * sc;
    }
    __syncthreads();
    const float* Asrc = g_hmax + (size_t)(b * 256) * NN;
    #pragma unroll
    for (int h = 0; h < 2; h++) {
        int r = ar + h * 8;
        float4 a = *(const float4*)&Asrc[(size_t)r * NN + n0 + ac];
        float sc = ssc[r], sh = ssh[r];
        a.x = fmaxf(a.x * sc + sh, 0.f); a.y = fmaxf(a.y * sc + sh, 0.f);
        a.z = fmaxf(a.z * sc + sh, 0.f); a.w = fmaxf(a.w * sc + sh, 0.f);
        *(float4*)&As[0][r][ac] = a;
    }
    *(float4*)&Bs[0][br_][bc] = *(const float4*)&g_W1T[br_ * C1v + o0 + bc];
    __syncthreads();
    float acc[4][4] = {};
    int buf = 0;
    for (int t = 0; t < 16; t++) {
        float4 a_reg[2], b_reg;
        if (t < 15) {
            int k0 = (t + 1) * 16;
            #pragma unroll
            for (int h = 0; h < 2; h++)
                a_reg[h] = *(const float4*)&Asrc[(size_t)(k0 + ar + h * 8) * NN + n0 + ac];
            b_reg = *(const float4*)&g_W1T[(k0 + br_) * C1v + o0 + bc];
        }
        #pragma unroll
        for (int kk = 0; kk < 16; kk++) {
            float4 a4 = *(const float4*)&As[buf][kk][tx * 4];
            float4 o4 = *(const float4*)&Bs[buf][kk][ty * 4];
            float ov[4] = {o4.x, o4.y, o4.z, o4.w};
            float nv[4] = {a4.x, a4.y, a4.z, a4.w};
            #pragma unroll
            for (int i = 0; i < 4; i++)
                #pragma unroll
                for (int q = 0; q < 4; q++) acc[i][q] += ov[i] * nv[q];
        }
        if (t < 15) {
            int k0 = (t + 1) * 16;
            #pragma unroll
            for (int h = 0; h < 2; h++) {
                int r = ar + h * 8;
                float sc = ssc[k0 + r], sh = ssh[k0 + r];
                a_reg[h].x = fmaxf(a_reg[h].x * sc + sh, 0.f);
                a_reg[h].y = fmaxf(a_reg[h].y * sc + sh, 0.f);
                a_reg[h].z = fmaxf(a_reg[h].z * sc + sh, 0.f);
                a_reg[h].w = fmaxf(a_reg[h].w * sc + sh, 0.f);
                *(float4*)&As[buf ^ 1][r][ac] = a_reg[h];
            }
            *(float4*)&Bs[buf ^ 1][br_][bc] = b_reg;
        }
        __syncthreads();
        buf ^= 1;
    }
    float psum[4], psq[4];
    #pragma unroll
    for (int i = 0; i < 4; i++) {
        int oy = o0 + ty * 4 + i;
        float bias = b1[oy];
        float s = 0.f, q = 0.f;
        #pragma unroll
        for (int jn = 0; jn < 4; jn++) {
            float h = acc[i][jn] + bias;
            acc[i][jn] = h; s += h; q += h * h;
        }
        psum[i] = s; psq[i] = q;
        float4 st = make_float4(acc[i][0], acc[i][1], acc[i][2], acc[i][3]);
        *(float4*)&g_h2[(size_t)(b * C1v + oy) * NN + n0 + tx * 4] = st;
    }
    #pragma unroll
    for (int i = 0; i < 4; i++) {
        #pragma unroll
        for (int off = 8; off > 0; off >>= 1) {
            psum[i] += __shfl_down_sync(0xffffffffu, psum[i], off, 16);
            psq[i]  += __shfl_down_sync(0xffffffffu, psq[i],  off, 16);
        }
    }
    if (tx == 0) {
        #pragma unroll
        for (int i = 0; i < 4; i++) {
            int oy = o0 + ty * 4 + i;
            atomicAdd(&g_stats[512 + oy], psum[i]);
            atomicAdd(&g_stats[640 + oy], psq[i]);
        }
    }
}

// ---------------- GEMM2: h3 = b2 + W2 @ relu(bn2(h2)), fused BN3 stats
// 64(n) x 32(o) tiles, 128 threads, 4x4 acc, double-buffered. grid=256.
__global__ void k_gemm2(const float* __restrict__ g1, const float* __restrict__ bt1,
                        const float* __restrict__ b2) {
    __shared__ float As[2][16][64];
    __shared__ float Bs[2][16][32];
    __shared__ float ssc[128], ssh[128];
    int b = blockIdx.z;
    int n0 = blockIdx.x * 64, o0 = blockIdx.y * 32;
    int tid = threadIdx.x;               // 128
    int tx = tid & 15, ty = tid >> 4;
    int ar = tid >> 4, ac = (tid & 15) * 4;
    int br_ = tid >> 3, bc = (tid & 7) * 4;
    {
        float m = g_stats[512 + tid] * (1.f / 4096.f);
        float v = g_stats[640 + tid] * (1.f / 4096.f) - m * m;
        float sc = g1[tid] * rsqrtf(v + EPSv);
        ssc[tid] = sc; ssh[tid] = bt1[tid] - m * sc;
    }
    __syncthreads();
    const float* Asrc = g_h2 + (size_t)(b * C1v) * NN;
    #pragma unroll
    for (int h = 0; h < 2; h++) {
        int r = ar + h * 8;
        float4 a = *(const float4*)&Asrc[(size_t)r * NN + n0 + ac];
        float sc = ssc[r], sh = ssh[r];
        a.x = fmaxf(a.x * sc + sh, 0.f); a.y = fmaxf(a.y * sc + sh, 0.f);
        a.z = fmaxf(a.z * sc + sh, 0.f); a.w = fmaxf(a.w * sc + sh, 0.f);
        *(float4*)&As[0][r][ac] = a;
    }
    *(float4*)&Bs[0][br_][bc] = *(const float4*)&g_W2T[br_ * C1v + o0 + bc];
    __syncthreads();
    float acc[4][4] = {};
    int buf = 0;
    for (int t = 0; t < 8; t++) {
        float4 a_reg[2], b_reg;
        if (t < 7) {
            int k0 = (t + 1) * 16;
            #pragma unroll
            for (int h = 0; h < 2; h++)
                a_reg[h] = *(const float4*)&Asrc[(size_t)(k0 + ar + h * 8) * NN + n0 + ac];
            b_reg = *(const float4*)&g_W2T[(k0 + br_) * C1v + o0 + bc];
        }
        #pragma unroll
        for (int kk = 0; kk < 16; kk++) {
            float4 a4 = *(const float4*)&As[buf][kk][tx * 4];
            float4 o4 = *(const float4*)&Bs[buf][kk][ty * 4];
            float ov[4] = {o4.x, o4.y, o4.z, o4.w};
            float nv[4] = {a4.x, a4.y, a4.z, a4.w};
            #pragma unroll
            for (int i = 0; i < 4; i++)
                #pragma unroll
                for (int q = 0; q < 4; q++) acc[i][q] += ov[i] * nv[q];
        }
        if (t < 7) {
            int k0 = (t + 1) * 16;
            #pragma unroll
            for (int h = 0; h < 2; h++) {
                int r = ar + h * 8;
                float sc = ssc[k0 + r], sh = ssh[k0 + r];
                a_reg[h].x = fmaxf(a_reg[h].x * sc + sh, 0.f);
                a_reg[h].y = fmaxf(a_reg[h].y * sc + sh, 0.f);
                a_reg[h].z = fmaxf(a_reg[h].z * sc + sh, 0.f);
                a_reg[h].w = fmaxf(a_reg[h].w * sc + sh, 0.f);
                *(float4*)&As[buf ^ 1][r][ac] = a_reg[h];
            }
            *(float4*)&Bs[buf ^ 1][br_][bc] = b_reg;
        }
        __syncthreads();
        buf ^= 1;
    }
    float psum[4], psq[4];
    #pragma unroll
    for (int i = 0; i < 4; i++) {
        int oy = o0 + ty * 4 + i;
        float bias = b2[oy];
        float s = 0.f, q = 0.f;
        #pragma unroll
        for (int jn = 0; jn < 4; jn++) {
            float h = acc[i][jn] + bias;
            acc[i][jn] = h; s += h; q += h * h;
        }
        psum[i] = s; psq[i] = q;
        float4 st = make_float4(acc[i][0], acc[i][1], acc[i][2], acc[i][3]);
        *(float4*)&g_h3[(size_t)(b * C1v + oy) * NN + n0 + tx * 4] = st;
    }
    #pragma unroll
    for (int i = 0; i < 4; i++) {
        #pragma unroll
        for (int off = 8; off > 0; off >>= 1) {
            psum[i] += __shfl_down_sync(0xffffffffu, psum[i], off, 16);
            psq[i]  += __shfl_down_sync(0xffffffffu, psq[i],  off, 16);
        }
    }
    if (tx == 0) {
        #pragma unroll
        for (int i = 0; i < 4; i++) {
            int oy = o0 + ty * 4 + i;
            atomicAdd(&g_stats[768 + oy], psum[i]);
            atomicAdd(&g_stats[896 + oy], psq[i]);
        }
    }
}

// ---------------- final feats: BN3+ReLU, tiled transpose (both writes coalesced) ----------------
__global__ void k_feats(const float* __restrict__ g2, const float* __restrict__ bt2,
                        float* __restrict__ out) {
    __shared__ float t[32][33];
    __shared__ float ssc[32], ssh[32];
    int b = blockIdx.z;
    int n0 = blockIdx.x * 32, o0 = blockIdx.y * 32;
    int tid = threadIdx.x;
    int tx = tid & 31, ty = tid >> 5;          // 32x8
    if (tid < 32) {
        int o = o0 + tid;
        float m = g_stats[768 + o] * (1.f / 4096.f);
        float v = g_stats[896 + o] * (1.f / 4096.f) - m * m;
        float sc = g2[o] * rsqrtf(v + EPSv);
        ssc[tid] = sc; ssh[tid] = bt2[o] - m * sc;
    }
    __syncthreads();
    #pragma unroll
    for (int r = 0; r < 4; r++) {
        int oo = ty + r * 8;
        int o = o0 + oo;
        size_t e = (size_t)(b * C1v + o) * NN + n0 + tx;
        float f = fmaxf(g_h3[e] * ssc[oo] + ssh[oo], 0.f);
        out[e] = f;
        t[oo][tx] = f;
    }
    __syncthreads();
    #pragma unroll
    for (int r = 0; r < 4; r++) {
        int nn = ty + r * 8;
        g_featsT[(size_t)(b * NN + n0 + nn) * C1v + o0 + tx] = t[tx][nn];
    }
}

// ---------------- RoI voxel max-pool: smem grid, parallel over points via smem atomicMax ----------------
__global__ void k_roipool(float* __restrict__ out) {
    extern __shared__ float sg[];            // 125*128 floats
    int br = blockIdx.x;
    int b = br >> 7;
    int t = threadIdx.x;                     // 512
    for (int i = t; i < 125 * C1v / 4; i += 512)
        ((float4*)sg)[i] = make_float4(0.f, 0.f, 0.f, 0.f);
    __syncthreads();
    const float* F = g_featsT + (size_t)b * NN * C1v;
    const int* lst = g_roilst + (size_t)br * NN;
    int m = g_roicnt[br];
    int ch = t & 127;
    int slot = t >> 7;                       // 0..3
    for (int e = slot; e < m; e += 4) {
        int pk = lst[e];
        int n = pk & 4095;
        int vox = pk >> 12;
        float val = F[(size_t)n * C1v + ch];
        atomicMax((int*)&sg[vox * C1v + ch], __float_as_int(val));
    }
    __syncthreads();
    float4* og = (float4*)(out + FEATS_SZ + (size_t)br * 125 * C1v);
    for (int i = t; i < 125 * C1v / 4; i += 512) og[i] = ((float4*)sg)[i];
}

// ---------------- launch ----------------
extern "C" void kernel_launch(void* const* d_in, const int* in_sizes, int n_in,
                              void* d_out, int out_size) {
    const float* pts    = (const float*)d_in[0];
    const float* feat   = (const float*)d_in[1];
    const float* rois   = (const float*)d_in[2];
    const float* W_mlp  = (const float*)d_in[3];
    const float* g_mlp  = (const float*)d_in[4];
    const float* btm    = (const float*)d_in[5];
    const float* W1     = (const float*)d_in[6];
    const float* b1     = (const float*)d_in[7];
    const float* g1     = (const float*)d_in[8];
    const float* bt1    = (const float*)d_in[9];
    const float* W2     = (const float*)d_in[10];
    const float* b2     = (const float*)d_in[11];
    const float* g2     = (const float*)d_in[12];
    const float* bt2    = (const float*)d_in[13];
    float* out = (float*)d_out;

    cudaFuncSetAttribute(k_roipool, cudaFuncAttributeMaxDynamicSharedMemorySize,
                         125 * C1v * sizeof(float));

    void* statsPtr = nullptr;
    cudaGetSymbolAddress(&statsPtr, g_stats);
    cudaMemsetAsync(statsPtr, 0, 1024 * sizeof(float), 0);

    k_front<<<1220, 256>>>(pts, rois, W_mlp, W1, W2);
    k_gemmG<<<dim3(NN / 64, 256 / 64, BB), 256>>>(feat);
    k_gathermax<<<dim3(NN / PPB, BB), 256>>>(pts);
    k_gemm1<<<dim3(NN / 64, C1v / 32, BB), 128>>>(g_mlp, btm, b1);
    k_gemm2<<<dim3(NN / 64, C1v / 32, BB), 128>>>(g1, bt1, b2);
    k_feats<<<dim3(NN / 32, C1v / 32, BB), 256>>>(g2, bt2, out);
    k_roipool<<<BB * RRoi, 512, 125 * C1v * sizeof(float)>>>(out);
}